// round 11
// baseline (speedup 1.0000x reference)
#include <cuda_runtime.h>
#include <math.h>

#define BB 2
#define QQ 2048
#define FF 1538
#define CH 314          // faces per smem chunk (5 chunks cover 1538), 25.1KB

__device__ float g_res[BB * QQ];
__device__ float g_partial[BB];
__device__ unsigned int g_done = 0;
__device__ float g_face[BB * FF * 20];   // 20 floats per face, 246KB

// ---------------------------------------------------------------------------
// fast helpers
// ---------------------------------------------------------------------------
__device__ __forceinline__ float sqrt_approx(float x) {
    float r; asm("sqrt.approx.f32 %0, %1;" : "=f"(r) : "f"(x)); return r;
}
__device__ __forceinline__ float rcp_approx(float x) {
    float r; asm("rcp.approx.f32 %0, %1;" : "=f"(r) : "f"(x)); return r;
}

// atan2 via quadrant folding + degree-11 odd minimax poly (|err| ~ 3e-6)
__device__ __forceinline__ float fast_atan2(float y, float x) {
    float ax = fabsf(x), ay = fabsf(y);
    float mx = fmaxf(ax, ay), mn = fminf(ax, ay);
    float t = mn * rcp_approx(mx);
    float s = t * t;
    float p =             -0.01172120f;
    p = fmaf(p, s,  0.05265332f);
    p = fmaf(p, s, -0.11643287f);
    p = fmaf(p, s,  0.19354346f);
    p = fmaf(p, s, -0.33262347f);
    p = fmaf(p, s,  0.99997726f);
    float r = p * t;
    if (ay > ax) r = 1.57079632679f - r;
    if (x < 0.0f) r = 3.14159265359f - r;
    return copysignf(r, y);
}

// ---------------------------------------------------------------------------
// Kernel 0: per-face precomputation (amortized across all 4096 queries).
// Layout per face (20 floats, 5 float4):
//   [0..3]   Ax Ay Az |A|^2
//   [4..7]   Bx By Bz |B|^2
//   [8..11]  Cx Cy Cz |C|^2
//   [12..15] Nx Ny Nz det      (N = (B-A)x(C-A), det = A.N = A.(BxC))
//   [16..19] dAB dBC dAC pad
// ---------------------------------------------------------------------------
__global__ void face_pre_kernel(const float* __restrict__ tris) {
    int f = blockIdx.x * 256 + threadIdx.x;
    if (f >= BB * FF) return;
    const float* t = tris + (size_t)f * 9;
    float Ax = t[0], Ay = t[1], Az = t[2];
    float Bx = t[3], By = t[4], Bz = t[5];
    float Cx = t[6], Cy = t[7], Cz = t[8];

    float e1x = Bx - Ax, e1y = By - Ay, e1z = Bz - Az;
    float e2x = Cx - Ax, e2y = Cy - Ay, e2z = Cz - Az;
    float Nx = e1y * e2z - e1z * e2y;
    float Ny = e1z * e2x - e1x * e2z;
    float Nz = e1x * e2y - e1y * e2x;
    float det = fmaf(Ax, Nx, fmaf(Ay, Ny, Az * Nz));

    float* o = g_face + (size_t)f * 20;
    o[0]  = Ax; o[1]  = Ay; o[2]  = Az;
    o[3]  = fmaf(Ax, Ax, fmaf(Ay, Ay, Az * Az));
    o[4]  = Bx; o[5]  = By; o[6]  = Bz;
    o[7]  = fmaf(Bx, Bx, fmaf(By, By, Bz * Bz));
    o[8]  = Cx; o[9]  = Cy; o[10] = Cz;
    o[11] = fmaf(Cx, Cx, fmaf(Cy, Cy, Cz * Cz));
    o[12] = Nx; o[13] = Ny; o[14] = Nz; o[15] = det;
    o[16] = fmaf(Ax, Bx, fmaf(Ay, By, Az * Bz));   // A.B
    o[17] = fmaf(Bx, Cx, fmaf(By, Cy, Bz * Cz));   // B.C
    o[18] = fmaf(Ax, Cx, fmaf(Ay, Cy, Az * Cz));   // A.C
    o[19] = 0.0f;
}

// ---------------------------------------------------------------------------
// Kernel 1: winding numbers + residuals (precomputed-face form).
// TWO queries per warp (ILP=2), TWO warps per query pair (face split).
// 128-thread blocks, 4 queries/block -> 1024 blocks.
// Per query per face: 9 fma (tA,tB,tC) + 6 (norms^2) + 3 sqrt + 4 (num)
//                     + 9 (dots) + 5 (den) + atan.
// ---------------------------------------------------------------------------
__global__ __launch_bounds__(128) void wn_kernel(const float* __restrict__ points,
                                                 const float* __restrict__ occ) {
    __shared__ float st[CH * 20];
    __shared__ float sacc[8];     // [warp*2 + whichQuery]

    int tid  = threadIdx.x;
    int warp = tid >> 5;          // 0..3
    int lane = tid & 31;
    int pair = warp >> 1;
    int half = warp & 1;

    int qA = blockIdx.x * 4 + pair * 2;   // 1024 blocks * 4 queries = 4096
    int qB = qA + 1;
    int b  = qA >> 11;

    float pxA = points[qA * 3 + 0], pyA = points[qA * 3 + 1], pzA = points[qA * 3 + 2];
    float pxB = points[qB * 3 + 0], pyB = points[qB * 3 + 1], pzB = points[qB * 3 + 2];
    float ppA = fmaf(pxA, pxA, fmaf(pyA, pyA, pzA * pzA));
    float ppB = fmaf(pxB, pxB, fmaf(pyB, pyB, pzB * pzB));

    const float* fb = g_face + (size_t)b * FF * 20;

    float accA = 0.0f, accB = 0.0f;
    for (int base = 0; base < FF; base += CH) {
        int nf = min(CH, FF - base);
        __syncthreads();
        // stage: 5 x float4 per face (both src and dst 16B-aligned)
        for (int f = tid; f < nf; f += 128) {
            const float4* src = (const float4*)(fb + (size_t)(base + f) * 20);
            float4* dst = (float4*)&st[f * 20];
            #pragma unroll
            for (int c = 0; c < 5; c++) dst[c] = src[c];
        }
        __syncthreads();

        for (int f = half * 32 + lane; f < nf; f += 64) {
            const float4* t4 = (const float4*)&st[f * 20];
            float4 va = t4[0];
            float4 vb = t4[1];
            float4 vc = t4[2];
            float4 vn = t4[3];
            float4 vd = t4[4];

            // ----- query A -----
            {
                float tA = fmaf(va.x, pxA, fmaf(va.y, pyA, va.z * pzA));
                float tB = fmaf(vb.x, pxA, fmaf(vb.y, pyA, vb.z * pzA));
                float tC = fmaf(vc.x, pxA, fmaf(vc.y, pyA, vc.z * pzA));

                float na = sqrt_approx(fmaf(-2.0f, tA, va.w + ppA));
                float nb = sqrt_approx(fmaf(-2.0f, tB, vb.w + ppA));
                float nc = sqrt_approx(fmaf(-2.0f, tC, vc.w + ppA));

                float num = vn.w - fmaf(vn.x, pxA, fmaf(vn.y, pyA, vn.z * pzA));
                float d01 = (vd.x + ppA) - (tA + tB);
                float d12 = (vd.y + ppA) - (tB + tC);
                float d02 = (vd.z + ppA) - (tA + tC);

                float den = fmaf(na * nb, nc, fmaf(d01, nc, fmaf(d02, nb, d12 * na)));
                accA += fast_atan2(num, den);
            }
            // ----- query B -----
            {
                float tA = fmaf(va.x, pxB, fmaf(va.y, pyB, va.z * pzB));
                float tB = fmaf(vb.x, pxB, fmaf(vb.y, pyB, vb.z * pzB));
                float tC = fmaf(vc.x, pxB, fmaf(vc.y, pyB, vc.z * pzB));

                float na = sqrt_approx(fmaf(-2.0f, tA, va.w + ppB));
                float nb = sqrt_approx(fmaf(-2.0f, tB, vb.w + ppB));
                float nc = sqrt_approx(fmaf(-2.0f, tC, vc.w + ppB));

                float num = vn.w - fmaf(vn.x, pxB, fmaf(vn.y, pyB, vn.z * pzB));
                float d01 = (vd.x + ppB) - (tA + tB);
                float d12 = (vd.y + ppB) - (tB + tC);
                float d02 = (vd.z + ppB) - (tA + tC);

                float den = fmaf(na * nb, nc, fmaf(d01, nc, fmaf(d02, nb, d12 * na)));
                accB += fast_atan2(num, den);
            }
        }
    }

    #pragma unroll
    for (int o = 16; o > 0; o >>= 1) {
        accA += __shfl_xor_sync(0xFFFFFFFFu, accA, o);
        accB += __shfl_xor_sync(0xFFFFFFFFu, accB, o);
    }

    if (lane == 0) {
        sacc[warp * 2 + 0] = accA;
        sacc[warp * 2 + 1] = accB;
    }
    __syncthreads();

    if (tid < 4) {
        int p    = tid >> 1;
        int qloc = tid & 1;
        float tot = sacc[(p * 2 + 0) * 2 + qloc] + sacc[(p * 2 + 1) * 2 + qloc];
        int q = blockIdx.x * 4 + tid;
        float wn = tot * 0.15915494309189535f;   // (2*atan2 sum)/(4*pi)
        g_res[q] = wn - occ[q];
    }
}

// ---------------------------------------------------------------------------
// Kernel 2: robust weighting. 1024 threads/batch. 8-bit radix-select with
// warp-aggregated (match_any) histogram atomics + early small-select.
// ---------------------------------------------------------------------------
__device__ __forceinline__ unsigned int fkey(float f) {
    unsigned int u = __float_as_uint(f);
    return (u & 0x80000000u) ? ~u : (u | 0x80000000u);
}
__device__ __forceinline__ float key_to_float(unsigned int k) {
    unsigned int bits = (k & 0x80000000u) ? (k ^ 0x80000000u) : ~k;
    return __uint_as_float(bits);
}

struct SelShared {
    unsigned int hist[256];
    unsigned int wtot[8];
    unsigned int bc[3];      // bin, new k, bin count / result value
    unsigned int cand[64];
    unsigned int ccnt;
};

__device__ unsigned int radix_select(const unsigned int* keys, SelShared* ss,
                                     int tid, int k) {
    int wid  = tid >> 5;
    int lane = tid & 31;
    unsigned int prefix = 0;

    for (int shift = 24; shift >= 0; shift -= 8) {
        if (tid < 256) ss->hist[tid] = 0;
        if (tid == 0)  ss->ccnt = 0;
        __syncthreads();

        unsigned int hi = (shift == 24) ? 0u : (0xFFFFFFFFu << (shift + 8));
        #pragma unroll
        for (int i = tid; i < QQ; i += 1024) {   // exactly 2 iterations
            unsigned int u = keys[i];
            bool ok = ((u & hi) == prefix);
            unsigned int bal = __ballot_sync(0xFFFFFFFFu, ok);
            if (ok) {
                unsigned int bin = (u >> shift) & 255u;
                unsigned int m = __match_any_sync(bal, bin);
                if (lane == __ffs(m) - 1)
                    atomicAdd(&ss->hist[bin], (unsigned int)__popc(m));
            }
        }
        __syncthreads();

        if (tid < 256) {
            unsigned int cnt = ss->hist[tid];
            unsigned int v   = cnt;
            #pragma unroll
            for (int o = 1; o < 32; o <<= 1) {
                unsigned int y = __shfl_up_sync(0xFFFFFFFFu, v, o);
                if (lane >= o) v += y;
            }
            if (lane == 31) ss->wtot[wid] = v;
            __syncthreads();

            if (wid == 0 && lane < 8) {
                unsigned int t0 = ss->wtot[lane];
                unsigned int t  = t0;
                #pragma unroll
                for (int o = 1; o < 8; o <<= 1) {
                    unsigned int y = __shfl_up_sync(0x000000FFu, t, o);
                    if (lane >= o) t += y;
                }
                ss->wtot[lane] = t - t0;
            }
            __syncthreads();

            unsigned int inc = v + ss->wtot[wid];
            unsigned int exc = inc - cnt;
            if ((int)exc <= k && k < (int)inc) {
                ss->bc[0] = (unsigned int)tid;
                ss->bc[1] = (unsigned int)(k - (int)exc);
                ss->bc[2] = cnt;
            }
        } else {
            __syncthreads();
            __syncthreads();
        }
        __syncthreads();

        prefix |= (ss->bc[0] << shift);
        k = (int)ss->bc[1];
        unsigned int cnt = ss->bc[2];

        if (shift > 0 && cnt <= 64u) {
            // gather candidates, warp-aggregated ccnt updates
            unsigned int hi2 = 0xFFFFFFFFu << shift;
            #pragma unroll
            for (int i = tid; i < QQ; i += 1024) {
                unsigned int u = keys[i];
                bool ok = ((u & hi2) == prefix);
                unsigned int bal = __ballot_sync(0xFFFFFFFFu, ok);
                if (ok) {
                    int leader = __ffs(bal) - 1;
                    int rank = __popc(bal & ((1u << lane) - 1u));
                    unsigned int basep = 0;
                    if (lane == leader)
                        basep = atomicAdd(&ss->ccnt, (unsigned int)__popc(bal));
                    basep = __shfl_sync(bal, basep, leader);
                    ss->cand[basep + rank] = u;
                }
            }
            __syncthreads();
            if (tid < 32) {
                int n = (int)cnt;
                for (int i = tid; i < n; i += 32) {
                    unsigned int v = ss->cand[i];
                    int less = 0, eq = 0;
                    for (int j = 0; j < n; j++) {
                        unsigned int u = ss->cand[j];
                        less += (u < v);
                        eq   += (u == v);
                    }
                    if (less <= k && k < less + eq) ss->bc[2] = v;
                }
            }
            __syncthreads();
            return ss->bc[2];
        }
        __syncthreads();
    }
    return prefix;
}

__global__ __launch_bounds__(1024) void robust_kernel(float* __restrict__ out) {
    __shared__ float        rs[QQ];
    __shared__ unsigned int keys[QQ];
    __shared__ SelShared    ss;
    __shared__ float        red[32];

    int b   = blockIdx.x;
    int tid = threadIdx.x;

    #pragma unroll
    for (int i = tid; i < QQ; i += 1024) {
        float v = g_res[b * QQ + i];
        rs[i]   = v;
        keys[i] = fkey(v);
    }
    __syncthreads();

    float med = key_to_float(radix_select(keys, &ss, tid, (QQ - 1) / 2));
    __syncthreads();

    #pragma unroll
    for (int i = tid; i < QQ; i += 1024)
        keys[i] = fkey(fabsf(rs[i] - med));
    __syncthreads();

    float mad = key_to_float(radix_select(keys, &ss, tid, (QQ - 1) / 2));

    float scale = (mad / 0.67449f) * 4.6851f;

    float sum = 0.0f;
    #pragma unroll
    for (int i = tid; i < QQ; i += 1024) {
        float r  = rs[i];
        float nr = r / scale;
        float t  = 1.0f - nr * nr;
        float w  = (nr >= 1.0f) ? 0.0f : t * t;
        sum += w * r * r;
    }

    #pragma unroll
    for (int o = 16; o > 0; o >>= 1)
        sum += __shfl_xor_sync(0xFFFFFFFFu, sum, o);
    if ((tid & 31) == 0) red[tid >> 5] = sum;
    __syncthreads();

    if (tid < 32) {
        float s = red[tid];
        #pragma unroll
        for (int o = 16; o > 0; o >>= 1)
            s += __shfl_xor_sync(0xFFFFFFFFu, s, o);
        if (tid == 0) {
            g_partial[b] = s;
            __threadfence();
            unsigned int prev = atomicAdd(&g_done, 1u);
            if (prev == BB - 1) {
                out[0] = 0.5f * (g_partial[0] + g_partial[1]);
                g_done = 0;  // reset for next graph replay
            }
        }
    }
}

extern "C" void kernel_launch(void* const* d_in, const int* in_sizes, int n_in,
                              void* d_out, int out_size) {
    const float* points = (const float*)d_in[0];  // (B,Q,3)
    const float* tris   = (const float*)d_in[1];  // (B,F,3,3)
    const float* occ    = (const float*)d_in[2];  // (B,Q)
    float* out = (float*)d_out;

    face_pre_kernel<<<(BB * FF + 255) / 256, 256>>>(tris);
    wn_kernel<<<(BB * QQ) / 4, 128>>>(points, occ);
    robust_kernel<<<BB, 1024>>>(out);
}

// round 12
// speedup vs baseline: 1.2449x; 1.2449x over previous
#include <cuda_runtime.h>
#include <math.h>

#define BB 2
#define QQ 2048
#define FF 1538
#define CH 514          // faces per smem chunk (3 chunks cover 1538)

__device__ float g_res[BB * QQ];
__device__ float g_partial[BB];
__device__ unsigned int g_done = 0;

// ---------------------------------------------------------------------------
// fast helpers
// ---------------------------------------------------------------------------
__device__ __forceinline__ float sqrt_approx(float x) {
    float r; asm("sqrt.approx.f32 %0, %1;" : "=f"(r) : "f"(x)); return r;
}
__device__ __forceinline__ float rcp_approx(float x) {
    float r; asm("rcp.approx.f32 %0, %1;" : "=f"(r) : "f"(x)); return r;
}

// atan2 via quadrant folding + degree-11 odd minimax poly (|err| ~ 3e-6)
__device__ __forceinline__ float fast_atan2(float y, float x) {
    float ax = fabsf(x), ay = fabsf(y);
    float mx = fmaxf(ax, ay), mn = fminf(ax, ay);
    float t = mn * rcp_approx(mx);
    float s = t * t;
    float p =             -0.01172120f;
    p = fmaf(p, s,  0.05265332f);
    p = fmaf(p, s, -0.11643287f);
    p = fmaf(p, s,  0.19354346f);
    p = fmaf(p, s, -0.33262347f);
    p = fmaf(p, s,  0.99997726f);
    float r = p * t;
    if (ay > ax) r = 1.57079632679f - r;
    if (x < 0.0f) r = 3.14159265359f - r;
    return copysignf(r, y);
}

// ---------------------------------------------------------------------------
// Kernel 1: winding numbers + residuals (proven R6 form).
// TWO queries per warp (ILP=2) and TWO warps per query pair (face split).
// 128-thread blocks, 4 queries/block -> 1024 blocks.
// ---------------------------------------------------------------------------
__global__ __launch_bounds__(128) void wn_kernel(const float* __restrict__ points,
                                                 const float* __restrict__ tris,
                                                 const float* __restrict__ occ) {
    __shared__ float st[CH * 12];
    __shared__ float sacc[8];     // [warp*2 + whichQuery]

    int tid  = threadIdx.x;
    int warp = tid >> 5;          // 0..3
    int lane = tid & 31;
    int pair = warp >> 1;         // query pair 0/1 within block
    int half = warp & 1;          // face-stride half

    int qA = blockIdx.x * 4 + pair * 2;   // 1024 blocks * 4 queries = 4096
    int qB = qA + 1;
    int b  = qA >> 11;                    // batch (uniform per block)

    float pxA = points[qA * 3 + 0], pyA = points[qA * 3 + 1], pzA = points[qA * 3 + 2];
    float pxB = points[qB * 3 + 0], pyB = points[qB * 3 + 1], pzB = points[qB * 3 + 2];

    const float* tb = tris + (size_t)b * FF * 9;

    float accA = 0.0f, accB = 0.0f;
    for (int base = 0; base < FF; base += CH) {
        int nf = min(CH, FF - base);
        __syncthreads();
        // stage: one face per thread, strided (no integer division)
        for (int f = tid; f < nf; f += 128) {
            const float* src = tb + (size_t)(base + f) * 9;
            float* dst = &st[f * 12];
            #pragma unroll
            for (int c = 0; c < 9; c++) dst[c] = src[c];
        }
        __syncthreads();

        for (int f = half * 32 + lane; f < nf; f += 64) {
            const float4* t4 = (const float4*)&st[f * 12];
            float4 v0 = t4[0];   // ax ay az bx
            float4 v1 = t4[1];   // by bz cx cy
            float4 v2 = t4[2];   // cz . . .

            // ----- query A -----
            {
                float ax = v0.x - pxA, ay = v0.y - pyA, az = v0.z - pzA;
                float bx = v0.w - pxA, by = v1.x - pyA, bz = v1.y - pzA;
                float cx = v1.z - pxA, cy = v1.w - pyA, cz = v2.x - pzA;

                float na = sqrt_approx(fmaf(ax, ax, fmaf(ay, ay, az * az)));
                float nb = sqrt_approx(fmaf(bx, bx, fmaf(by, by, bz * bz)));
                float nc = sqrt_approx(fmaf(cx, cx, fmaf(cy, cy, cz * cz)));

                float crx = by * cz - bz * cy;
                float cry = bz * cx - bx * cz;
                float crz = bx * cy - by * cx;

                float num = fmaf(ax, crx, fmaf(ay, cry, az * crz));
                float d01 = fmaf(ax, bx, fmaf(ay, by, az * bz));
                float d12 = fmaf(bx, cx, fmaf(by, cy, bz * cz));
                float d02 = fmaf(ax, cx, fmaf(ay, cy, az * cz));

                float den = fmaf(na * nb, nc, fmaf(d01, nc, fmaf(d02, nb, d12 * na)));
                accA += fast_atan2(num, den);
            }
            // ----- query B -----
            {
                float ax = v0.x - pxB, ay = v0.y - pyB, az = v0.z - pzB;
                float bx = v0.w - pxB, by = v1.x - pyB, bz = v1.y - pzB;
                float cx = v1.z - pxB, cy = v1.w - pyB, cz = v2.x - pzB;

                float na = sqrt_approx(fmaf(ax, ax, fmaf(ay, ay, az * az)));
                float nb = sqrt_approx(fmaf(bx, bx, fmaf(by, by, bz * bz)));
                float nc = sqrt_approx(fmaf(cx, cx, fmaf(cy, cy, cz * cz)));

                float crx = by * cz - bz * cy;
                float cry = bz * cx - bx * cz;
                float crz = bx * cy - by * cx;

                float num = fmaf(ax, crx, fmaf(ay, cry, az * crz));
                float d01 = fmaf(ax, bx, fmaf(ay, by, az * bz));
                float d12 = fmaf(bx, cx, fmaf(by, cy, bz * cz));
                float d02 = fmaf(ax, cx, fmaf(ay, cy, az * cz));

                float den = fmaf(na * nb, nc, fmaf(d01, nc, fmaf(d02, nb, d12 * na)));
                accB += fast_atan2(num, den);
            }
        }
    }

    #pragma unroll
    for (int o = 16; o > 0; o >>= 1) {
        accA += __shfl_xor_sync(0xFFFFFFFFu, accA, o);
        accB += __shfl_xor_sync(0xFFFFFFFFu, accB, o);
    }

    if (lane == 0) {
        sacc[warp * 2 + 0] = accA;
        sacc[warp * 2 + 1] = accB;
    }
    __syncthreads();

    if (tid < 4) {  // tid = local query index 0..3
        int p    = tid >> 1;
        int qloc = tid & 1;
        float tot = sacc[(p * 2 + 0) * 2 + qloc] + sacc[(p * 2 + 1) * 2 + qloc];
        int q = blockIdx.x * 4 + tid;
        float wn = tot * 0.15915494309189535f;   // (2*atan2 sum)/(4*pi)
        g_res[q] = wn - occ[q];
    }
}

// ---------------------------------------------------------------------------
// Kernel 2: robust weighting. 1024 threads/batch. 8-bit radix-select with
// warp-aggregated (match_any) histogram atomics + early small-select.
// ---------------------------------------------------------------------------
__device__ __forceinline__ unsigned int fkey(float f) {
    unsigned int u = __float_as_uint(f);
    return (u & 0x80000000u) ? ~u : (u | 0x80000000u);
}
__device__ __forceinline__ float key_to_float(unsigned int k) {
    unsigned int bits = (k & 0x80000000u) ? (k ^ 0x80000000u) : ~k;
    return __uint_as_float(bits);
}

struct SelShared {
    unsigned int hist[256];
    unsigned int wtot[8];
    unsigned int bc[3];      // bin, new k, bin count / result value
    unsigned int cand[64];
    unsigned int ccnt;
};

__device__ unsigned int radix_select(const unsigned int* keys, SelShared* ss,
                                     int tid, int k) {
    int wid  = tid >> 5;
    int lane = tid & 31;
    unsigned int prefix = 0;

    for (int shift = 24; shift >= 0; shift -= 8) {
        if (tid < 256) ss->hist[tid] = 0;
        if (tid == 0)  ss->ccnt = 0;
        __syncthreads();

        unsigned int hi = (shift == 24) ? 0u : (0xFFFFFFFFu << (shift + 8));
        #pragma unroll
        for (int i = tid; i < QQ; i += 1024) {   // exactly 2 iterations
            unsigned int u = keys[i];
            bool ok = ((u & hi) == prefix);
            unsigned int bal = __ballot_sync(0xFFFFFFFFu, ok);
            if (ok) {
                unsigned int bin = (u >> shift) & 255u;
                unsigned int m = __match_any_sync(bal, bin);
                if (lane == __ffs(m) - 1)
                    atomicAdd(&ss->hist[bin], (unsigned int)__popc(m));
            }
        }
        __syncthreads();

        if (tid < 256) {
            unsigned int cnt = ss->hist[tid];
            unsigned int v   = cnt;
            #pragma unroll
            for (int o = 1; o < 32; o <<= 1) {
                unsigned int y = __shfl_up_sync(0xFFFFFFFFu, v, o);
                if (lane >= o) v += y;
            }
            if (lane == 31) ss->wtot[wid] = v;
            __syncthreads();

            if (wid == 0 && lane < 8) {
                unsigned int t0 = ss->wtot[lane];
                unsigned int t  = t0;
                #pragma unroll
                for (int o = 1; o < 8; o <<= 1) {
                    unsigned int y = __shfl_up_sync(0x000000FFu, t, o);
                    if (lane >= o) t += y;
                }
                ss->wtot[lane] = t - t0;
            }
            __syncthreads();

            unsigned int inc = v + ss->wtot[wid];
            unsigned int exc = inc - cnt;
            if ((int)exc <= k && k < (int)inc) {
                ss->bc[0] = (unsigned int)tid;
                ss->bc[1] = (unsigned int)(k - (int)exc);
                ss->bc[2] = cnt;
            }
        } else {
            __syncthreads();
            __syncthreads();
        }
        __syncthreads();

        prefix |= (ss->bc[0] << shift);
        k = (int)ss->bc[1];
        unsigned int cnt = ss->bc[2];

        if (shift > 0 && cnt <= 64u) {
            // gather candidates, warp-aggregated ccnt updates
            unsigned int hi2 = 0xFFFFFFFFu << shift;
            #pragma unroll
            for (int i = tid; i < QQ; i += 1024) {
                unsigned int u = keys[i];
                bool ok = ((u & hi2) == prefix);
                unsigned int bal = __ballot_sync(0xFFFFFFFFu, ok);
                if (ok) {
                    int leader = __ffs(bal) - 1;
                    int rank = __popc(bal & ((1u << lane) - 1u));
                    unsigned int basep = 0;
                    if (lane == leader)
                        basep = atomicAdd(&ss->ccnt, (unsigned int)__popc(bal));
                    basep = __shfl_sync(bal, basep, leader);
                    ss->cand[basep + rank] = u;
                }
            }
            __syncthreads();
            if (tid < 32) {
                int n = (int)cnt;
                for (int i = tid; i < n; i += 32) {
                    unsigned int v = ss->cand[i];
                    int less = 0, eq = 0;
                    for (int j = 0; j < n; j++) {
                        unsigned int u = ss->cand[j];
                        less += (u < v);
                        eq   += (u == v);
                    }
                    if (less <= k && k < less + eq) ss->bc[2] = v;
                }
            }
            __syncthreads();
            return ss->bc[2];
        }
        __syncthreads();
    }
    return prefix;
}

__global__ __launch_bounds__(1024) void robust_kernel(float* __restrict__ out) {
    __shared__ float        rs[QQ];
    __shared__ unsigned int keys[QQ];
    __shared__ SelShared    ss;
    __shared__ float        red[32];

    int b   = blockIdx.x;
    int tid = threadIdx.x;

    #pragma unroll
    for (int i = tid; i < QQ; i += 1024) {
        float v = g_res[b * QQ + i];
        rs[i]   = v;
        keys[i] = fkey(v);
    }
    __syncthreads();

    float med = key_to_float(radix_select(keys, &ss, tid, (QQ - 1) / 2));
    __syncthreads();

    #pragma unroll
    for (int i = tid; i < QQ; i += 1024)
        keys[i] = fkey(fabsf(rs[i] - med));
    __syncthreads();

    float mad = key_to_float(radix_select(keys, &ss, tid, (QQ - 1) / 2));

    float scale = (mad / 0.67449f) * 4.6851f;

    float sum = 0.0f;
    #pragma unroll
    for (int i = tid; i < QQ; i += 1024) {
        float r  = rs[i];
        float nr = r / scale;
        float t  = 1.0f - nr * nr;
        float w  = (nr >= 1.0f) ? 0.0f : t * t;
        sum += w * r * r;
    }

    #pragma unroll
    for (int o = 16; o > 0; o >>= 1)
        sum += __shfl_xor_sync(0xFFFFFFFFu, sum, o);
    if ((tid & 31) == 0) red[tid >> 5] = sum;
    __syncthreads();

    if (tid < 32) {
        float s = red[tid];
        #pragma unroll
        for (int o = 16; o > 0; o >>= 1)
            s += __shfl_xor_sync(0xFFFFFFFFu, s, o);
        if (tid == 0) {
            g_partial[b] = s;
            __threadfence();
            unsigned int prev = atomicAdd(&g_done, 1u);
            if (prev == BB - 1) {
                out[0] = 0.5f * (g_partial[0] + g_partial[1]);
                g_done = 0;  // reset for next graph replay
            }
        }
    }
}

extern "C" void kernel_launch(void* const* d_in, const int* in_sizes, int n_in,
                              void* d_out, int out_size) {
    const float* points = (const float*)d_in[0];  // (B,Q,3)
    const float* tris   = (const float*)d_in[1];  // (B,F,3,3)
    const float* occ    = (const float*)d_in[2];  // (B,Q)
    float* out = (float*)d_out;

    wn_kernel<<<(BB * QQ) / 4, 128>>>(points, tris, occ);
    robust_kernel<<<BB, 1024>>>(out);
}

// round 13
// speedup vs baseline: 1.4269x; 1.1462x over previous
#include <cuda_runtime.h>
#include <math.h>

#define BB 2
#define QQ 2048
#define FF 1538
#define CH 514          // faces per smem chunk (3 chunks cover 1538)

__device__ float g_res[BB * QQ];
__device__ float g_partial[BB];
__device__ unsigned int g_done = 0;

// ---------------------------------------------------------------------------
// fast helpers
// ---------------------------------------------------------------------------
__device__ __forceinline__ float sqrt_approx(float x) {
    float r; asm("sqrt.approx.f32 %0, %1;" : "=f"(r) : "f"(x)); return r;
}
__device__ __forceinline__ float rcp_approx(float x) {
    float r; asm("rcp.approx.f32 %0, %1;" : "=f"(r) : "f"(x)); return r;
}

// atan2 via quadrant folding + degree-11 odd minimax poly (|err| ~ 3e-6)
__device__ __forceinline__ float fast_atan2(float y, float x) {
    float ax = fabsf(x), ay = fabsf(y);
    float mx = fmaxf(ax, ay), mn = fminf(ax, ay);
    float t = mn * rcp_approx(mx);
    float s = t * t;
    float p =             -0.01172120f;
    p = fmaf(p, s,  0.05265332f);
    p = fmaf(p, s, -0.11643287f);
    p = fmaf(p, s,  0.19354346f);
    p = fmaf(p, s, -0.33262347f);
    p = fmaf(p, s,  0.99997726f);
    float r = p * t;
    if (ay > ax) r = 1.57079632679f - r;
    if (x < 0.0f) r = 3.14159265359f - r;
    return copysignf(r, y);
}

// one face (from smem float4s) against one query point -> solid-angle atan term
__device__ __forceinline__ float face_term(const float4 v0, const float4 v1,
                                           const float4 v2,
                                           float px, float py, float pz) {
    float ax = v0.x - px, ay = v0.y - py, az = v0.z - pz;
    float bx = v0.w - px, by = v1.x - py, bz = v1.y - pz;
    float cx = v1.z - px, cy = v1.w - py, cz = v2.x - pz;

    float na = sqrt_approx(fmaf(ax, ax, fmaf(ay, ay, az * az)));
    float nb = sqrt_approx(fmaf(bx, bx, fmaf(by, by, bz * bz)));
    float nc = sqrt_approx(fmaf(cx, cx, fmaf(cy, cy, cz * cz)));

    float crx = by * cz - bz * cy;
    float cry = bz * cx - bx * cz;
    float crz = bx * cy - by * cx;

    float num = fmaf(ax, crx, fmaf(ay, cry, az * crz));
    float d01 = fmaf(ax, bx, fmaf(ay, by, az * bz));
    float d12 = fmaf(bx, cx, fmaf(by, cy, bz * cz));
    float d02 = fmaf(ax, cx, fmaf(ay, cy, az * cz));

    float den = fmaf(na * nb, nc, fmaf(d01, nc, fmaf(d02, nb, d12 * na)));
    return fast_atan2(num, den);
}

// ---------------------------------------------------------------------------
// Kernel 1: winding numbers + residuals (R6 form + face-level unroll 2).
// TWO queries per warp (ILP=2) and TWO warps per query pair (face split).
// 128-thread blocks, 4 queries/block -> 1024 blocks.
// ---------------------------------------------------------------------------
__global__ __launch_bounds__(128) void wn_kernel(const float* __restrict__ points,
                                                 const float* __restrict__ tris,
                                                 const float* __restrict__ occ) {
    __shared__ float st[CH * 12];
    __shared__ float sacc[8];     // [warp*2 + whichQuery]

    int tid  = threadIdx.x;
    int warp = tid >> 5;          // 0..3
    int lane = tid & 31;
    int pair = warp >> 1;         // query pair 0/1 within block
    int half = warp & 1;          // face-stride half

    int qA = blockIdx.x * 4 + pair * 2;   // 1024 blocks * 4 queries = 4096
    int qB = qA + 1;
    int b  = qA >> 11;                    // batch (uniform per block)

    float pxA = points[qA * 3 + 0], pyA = points[qA * 3 + 1], pzA = points[qA * 3 + 2];
    float pxB = points[qB * 3 + 0], pyB = points[qB * 3 + 1], pzB = points[qB * 3 + 2];

    const float* tb = tris + (size_t)b * FF * 9;

    float accA = 0.0f, accB = 0.0f;
    for (int base = 0; base < FF; base += CH) {
        int nf = min(CH, FF - base);
        __syncthreads();
        // stage: one face per thread, strided (no integer division)
        for (int f = tid; f < nf; f += 128) {
            const float* src = tb + (size_t)(base + f) * 9;
            float* dst = &st[f * 12];
            #pragma unroll
            for (int c = 0; c < 9; c++) dst[c] = src[c];
        }
        __syncthreads();

        int f = half * 32 + lane;
        // unrolled-by-2: two faces in flight -> 4 independent chains/lane
        for (; f + 64 < nf; f += 128) {
            const float4* t4a = (const float4*)&st[f * 12];
            float4 u0 = t4a[0], u1 = t4a[1], u2 = t4a[2];
            const float4* t4b = (const float4*)&st[(f + 64) * 12];
            float4 w0 = t4b[0], w1 = t4b[1], w2 = t4b[2];

            accA += face_term(u0, u1, u2, pxA, pyA, pzA);
            accB += face_term(u0, u1, u2, pxB, pyB, pzB);
            accA += face_term(w0, w1, w2, pxA, pyA, pzA);
            accB += face_term(w0, w1, w2, pxB, pyB, pzB);
        }
        for (; f < nf; f += 64) {
            const float4* t4 = (const float4*)&st[f * 12];
            float4 v0 = t4[0], v1 = t4[1], v2 = t4[2];
            accA += face_term(v0, v1, v2, pxA, pyA, pzA);
            accB += face_term(v0, v1, v2, pxB, pyB, pzB);
        }
    }

    #pragma unroll
    for (int o = 16; o > 0; o >>= 1) {
        accA += __shfl_xor_sync(0xFFFFFFFFu, accA, o);
        accB += __shfl_xor_sync(0xFFFFFFFFu, accB, o);
    }

    if (lane == 0) {
        sacc[warp * 2 + 0] = accA;
        sacc[warp * 2 + 1] = accB;
    }
    __syncthreads();

    if (tid < 4) {  // tid = local query index 0..3
        int p    = tid >> 1;
        int qloc = tid & 1;
        float tot = sacc[(p * 2 + 0) * 2 + qloc] + sacc[(p * 2 + 1) * 2 + qloc];
        int q = blockIdx.x * 4 + tid;
        float wn = tot * 0.15915494309189535f;   // (2*atan2 sum)/(4*pi)
        g_res[q] = wn - occ[q];
    }
}

// ---------------------------------------------------------------------------
// Kernel 2: robust weighting (EXACT R6 version, proven 10.0us).
// 1024 threads/batch; 8-bit radix-select + early small-select (<=64).
// ---------------------------------------------------------------------------
__device__ __forceinline__ unsigned int fkey(float f) {
    unsigned int u = __float_as_uint(f);
    return (u & 0x80000000u) ? ~u : (u | 0x80000000u);
}
__device__ __forceinline__ float key_to_float(unsigned int k) {
    unsigned int bits = (k & 0x80000000u) ? (k ^ 0x80000000u) : ~k;
    return __uint_as_float(bits);
}

struct SelShared {
    unsigned int hist[256];
    unsigned int wtot[8];
    unsigned int bc[3];      // bin, new k, bin count / result value
    unsigned int cand[64];
    unsigned int ccnt;
};

__device__ unsigned int radix_select(const unsigned int* keys, SelShared* ss,
                                     int tid, int k) {
    int wid  = tid >> 5;
    int lane = tid & 31;
    unsigned int prefix = 0;

    for (int shift = 24; shift >= 0; shift -= 8) {
        if (tid < 256) ss->hist[tid] = 0;
        if (tid == 0)  ss->ccnt = 0;
        __syncthreads();

        unsigned int hi = (shift == 24) ? 0u : (0xFFFFFFFFu << (shift + 8));
        #pragma unroll
        for (int i = tid; i < QQ; i += 1024) {
            unsigned int u = keys[i];
            if ((u & hi) == prefix) atomicAdd(&ss->hist[(u >> shift) & 255u], 1u);
        }
        __syncthreads();

        if (tid < 256) {
            unsigned int cnt = ss->hist[tid];
            unsigned int v   = cnt;
            #pragma unroll
            for (int o = 1; o < 32; o <<= 1) {
                unsigned int y = __shfl_up_sync(0xFFFFFFFFu, v, o);
                if (lane >= o) v += y;
            }
            if (lane == 31) ss->wtot[wid] = v;
            __syncthreads();

            if (wid == 0 && lane < 8) {
                unsigned int t0 = ss->wtot[lane];
                unsigned int t  = t0;
                #pragma unroll
                for (int o = 1; o < 8; o <<= 1) {
                    unsigned int y = __shfl_up_sync(0x000000FFu, t, o);
                    if (lane >= o) t += y;
                }
                ss->wtot[lane] = t - t0;
            }
            __syncthreads();

            unsigned int inc = v + ss->wtot[wid];
            unsigned int exc = inc - cnt;
            if ((int)exc <= k && k < (int)inc) {
                ss->bc[0] = (unsigned int)tid;
                ss->bc[1] = (unsigned int)(k - (int)exc);
                ss->bc[2] = cnt;
            }
        } else {
            __syncthreads();
            __syncthreads();
        }
        __syncthreads();

        prefix |= (ss->bc[0] << shift);
        k = (int)ss->bc[1];
        unsigned int cnt = ss->bc[2];

        if (shift > 0 && cnt <= 64u) {
            unsigned int hi2 = 0xFFFFFFFFu << shift;
            #pragma unroll
            for (int i = tid; i < QQ; i += 1024) {
                unsigned int u = keys[i];
                if ((u & hi2) == prefix) {
                    unsigned int p = atomicAdd(&ss->ccnt, 1u);
                    ss->cand[p] = u;
                }
            }
            __syncthreads();
            if (tid < 32) {
                int n = (int)cnt;
                for (int i = tid; i < n; i += 32) {
                    unsigned int v = ss->cand[i];
                    int less = 0, eq = 0;
                    for (int j = 0; j < n; j++) {
                        unsigned int u = ss->cand[j];
                        less += (u < v);
                        eq   += (u == v);
                    }
                    if (less <= k && k < less + eq) ss->bc[2] = v;
                }
            }
            __syncthreads();
            return ss->bc[2];
        }
        __syncthreads();
    }
    return prefix;
}

__global__ __launch_bounds__(1024) void robust_kernel(float* __restrict__ out) {
    __shared__ float        rs[QQ];
    __shared__ unsigned int keys[QQ];
    __shared__ SelShared    ss;
    __shared__ float        red[32];

    int b   = blockIdx.x;
    int tid = threadIdx.x;

    #pragma unroll
    for (int i = tid; i < QQ; i += 1024) {
        float v = g_res[b * QQ + i];
        rs[i]   = v;
        keys[i] = fkey(v);
    }
    __syncthreads();

    float med = key_to_float(radix_select(keys, &ss, tid, (QQ - 1) / 2));
    __syncthreads();

    #pragma unroll
    for (int i = tid; i < QQ; i += 1024)
        keys[i] = fkey(fabsf(rs[i] - med));
    __syncthreads();

    float mad = key_to_float(radix_select(keys, &ss, tid, (QQ - 1) / 2));

    float scale = (mad / 0.67449f) * 4.6851f;

    float sum = 0.0f;
    #pragma unroll
    for (int i = tid; i < QQ; i += 1024) {
        float r  = rs[i];
        float nr = r / scale;
        float t  = 1.0f - nr * nr;
        float w  = (nr >= 1.0f) ? 0.0f : t * t;
        sum += w * r * r;
    }

    #pragma unroll
    for (int o = 16; o > 0; o >>= 1)
        sum += __shfl_xor_sync(0xFFFFFFFFu, sum, o);
    if ((tid & 31) == 0) red[tid >> 5] = sum;
    __syncthreads();

    if (tid < 32) {
        float s = red[tid];
        #pragma unroll
        for (int o = 16; o > 0; o >>= 1)
            s += __shfl_xor_sync(0xFFFFFFFFu, s, o);
        if (tid == 0) {
            g_partial[b] = s;
            __threadfence();
            unsigned int prev = atomicAdd(&g_done, 1u);
            if (prev == BB - 1) {
                out[0] = 0.5f * (g_partial[0] + g_partial[1]);
                g_done = 0;  // reset for next graph replay
            }
        }
    }
}

extern "C" void kernel_launch(void* const* d_in, const int* in_sizes, int n_in,
                              void* d_out, int out_size) {
    const float* points = (const float*)d_in[0];  // (B,Q,3)
    const float* tris   = (const float*)d_in[1];  // (B,F,3,3)
    const float* occ    = (const float*)d_in[2];  // (B,Q)
    float* out = (float*)d_out;

    wn_kernel<<<(BB * QQ) / 4, 128>>>(points, tris, occ);
    robust_kernel<<<BB, 1024>>>(out);
}